// round 14
// baseline (speedup 1.0000x reference)
#include <cuda_runtime.h>

#define B_     32
#define C_     3
#define H_     512
#define W_     512
#define HW_    (H_ * W_)
#define TPB    256
#define NBLK   512                 // single wave at 4 CTAs/SM
#define WROWS  16                  // rows per warp task

__device__ float g_accum = 0.0f;
__device__ unsigned int g_count = 0;

struct RowD { float4 d; float dl, dr; };

// scalar gray-diff at element offset `off` within one image
__device__ __forceinline__ float gray1(const float* __restrict__ s,
                                       const float* __restrict__ h, size_t off)
{
    return 0.2989f * (s[off]           - h[off])
         + 0.587f  * (s[off +     HW_] - h[off +     HW_])
         + 0.114f  * (s[off + 2 * HW_] - h[off + 2 * HW_]);
}

__device__ __forceinline__ RowD load_row(const float* __restrict__ srb,
                                         const float* __restrict__ hrb,
                                         int row, int c4, int lane)
{
    RowD r;
    if (row < 0 || row >= H_) {           // warp-uniform branch
        r.d = make_float4(0.f, 0.f, 0.f, 0.f);
        r.dl = 0.f; r.dr = 0.f;
        return r;
    }
    size_t off = (size_t)row * W_ + c4;
    float4 s0 = *(const float4*)(srb + off);
    float4 s1 = *(const float4*)(srb + off + HW_);
    float4 s2 = *(const float4*)(srb + off + 2 * HW_);
    float4 h0 = *(const float4*)(hrb + off);
    float4 h1 = *(const float4*)(hrb + off + HW_);
    float4 h2 = *(const float4*)(hrb + off + 2 * HW_);
    r.d.x = 0.2989f * (s0.x - h0.x) + 0.587f * (s1.x - h1.x) + 0.114f * (s2.x - h2.x);
    r.d.y = 0.2989f * (s0.y - h0.y) + 0.587f * (s1.y - h1.y) + 0.114f * (s2.y - h2.y);
    r.d.z = 0.2989f * (s0.z - h0.z) + 0.587f * (s1.z - h1.z) + 0.114f * (s2.z - h2.z);
    r.d.w = 0.2989f * (s0.w - h0.w) + 0.587f * (s1.w - h1.w) + 0.114f * (s2.w - h2.w);

    r.dl = __shfl_up_sync(0xFFFFFFFFu, r.d.w, 1);
    r.dr = __shfl_down_sync(0xFFFFFFFFu, r.d.x, 1);
    if (lane == 0)
        r.dl = (c4 == 0)      ? 0.f : gray1(srb, hrb, off - 1);
    if (lane == 31)
        r.dr = (c4 + 4 == W_) ? 0.f : gray1(srb, hrb, off + 4);
    return r;
}

__device__ __forceinline__ float sobel4(const RowD& t, const RowD& m, const RowD& b)
{
    float acc;
    {
        float gx = (t.dl - t.d.y) + 2.0f * (m.dl - m.d.y) + (b.dl - b.d.y);
        float gy = (t.dl + 2.0f * t.d.x + t.d.y) - (b.dl + 2.0f * b.d.x + b.d.y);
        acc = fabsf(gx) + fabsf(gy);
    }
    {
        float gx = (t.d.x - t.d.z) + 2.0f * (m.d.x - m.d.z) + (b.d.x - b.d.z);
        float gy = (t.d.x + 2.0f * t.d.y + t.d.z) - (b.d.x + 2.0f * b.d.y + b.d.z);
        acc += fabsf(gx) + fabsf(gy);
    }
    {
        float gx = (t.d.y - t.d.w) + 2.0f * (m.d.y - m.d.w) + (b.d.y - b.d.w);
        float gy = (t.d.y + 2.0f * t.d.z + t.d.w) - (b.d.y + 2.0f * b.d.z + b.d.w);
        acc += fabsf(gx) + fabsf(gy);
    }
    {
        float gx = (t.d.z - t.dr) + 2.0f * (m.d.z - m.dr) + (b.d.z - b.dr);
        float gy = (t.d.z + 2.0f * t.d.w + t.dr) - (b.d.z + 2.0f * b.d.w + b.dr);
        acc += fabsf(gx) + fabsf(gy);
    }
    return acc;
}

__global__ __launch_bounds__(TPB, 4) void edge_loss_kernel(
    const float* __restrict__ sr, const float* __restrict__ hr,
    float* __restrict__ out)
{
    const int tid  = threadIdx.x;
    const int lane = tid & 31;
    const int wid  = tid >> 5;          // 0..7

    // CTA -> (b, strip, superband): 32 * 4 * 4 = 512
    const int b     = blockIdx.x >> 4;
    const int rem   = blockIdx.x & 15;
    const int strip = rem >> 2;         // 0..3 (128-col strips)
    const int sband = rem & 3;          // 0..3 (128-row superbands)

    const int r0 = sband * 128 + wid * WROWS;
    const int c4 = strip * 128 + lane * 4;

    const float* srb = sr + (size_t)b * C_ * HW_;
    const float* hrb = hr + (size_t)b * C_ * HW_;

    // Each warp: 16 rows. Per row: 3 independent row loads (18 LDG.128) -> sobel.
    // Adjacent iterations share 2 of 3 rows -> L1 hits; no smem, no barriers.
    float acc = 0.0f;
    #pragma unroll 2
    for (int i = 0; i < WROWS; ++i) {
        int row = r0 + i;
        RowD t = load_row(srb, hrb, row - 1, c4, lane);
        RowD m = load_row(srb, hrb, row,     c4, lane);
        RowD bt = load_row(srb, hrb, row + 1, c4, lane);
        acc += sobel4(t, m, bt);
    }

    // Block reduce
    #pragma unroll
    for (int off = 16; off > 0; off >>= 1)
        acc += __shfl_xor_sync(0xFFFFFFFFu, acc, off);

    __shared__ float wsum[TPB / 32];
    if (lane == 0) wsum[wid] = acc;
    __syncthreads();

    // tid0: one fire-and-forget atomic per block; NO trailing barrier.
    if (tid == 0) {
        float s = 0.0f;
        #pragma unroll
        for (int w = 0; w < TPB / 32; ++w) s += wsum[w];
        atomicAdd(&g_accum, s);
        __threadfence();
        unsigned int prev = atomicAdd(&g_count, 1u);
        if (prev == NBLK - 1) {
            float tot = atomicAdd(&g_accum, 0.0f);   // coherent L2 read
            out[0] = tot / (float)(B_ * (size_t)HW_);
            g_accum = 0.0f;   // reset for next replay
            g_count = 0;
        }
    }
}

extern "C" void kernel_launch(void* const* d_in, const int* in_sizes, int n_in,
                              void* d_out, int out_size)
{
    const float* sr = (const float*)d_in[0];
    const float* hr = (const float*)d_in[1];
    float* out = (float*)d_out;

    edge_loss_kernel<<<NBLK, TPB>>>(sr, hr, out);
}

// round 15
// speedup vs baseline: 1.0191x; 1.0191x over previous
#include <cuda_runtime.h>
#include <cuda_fp16.h>

#define B_   32
#define C_   3
#define H_   512
#define W_   512
#define HW_  (H_ * W_)
#define ROWS 16
#define HB_  (H_ / ROWS)          // 32 row-bands per image
#define NBLK (B_ * HB_)           // 1024 blocks
#define TPB  256
#define TROWS (ROWS + 2)          // 18 tile rows (with halo)

// smem: per tile row, 512 pixels x half2{h1,h2} = 2048 B. 18 rows = 36,864 B.
#define RSTR 512                  // row stride in half2 units

__device__ float g_accum = 0.0f;
__device__ unsigned int g_count = 0;

__device__ __forceinline__ float gray1(const float* __restrict__ s,
                                       const float* __restrict__ h, size_t off)
{
    return 0.2989f * (s[off]           - h[off])
         + 0.587f  * (s[off +     HW_] - h[off +     HW_])
         + 0.114f  * (s[off + 2 * HW_] - h[off + 2 * HW_]);
}

__global__ __launch_bounds__(TPB, 6) void edge_loss_kernel(
    const float* __restrict__ sr, const float* __restrict__ hr,
    float* __restrict__ out)
{
    __shared__ __half2 g[TROWS * RSTR];   // 36,864 B -> 6 CTAs/SM

    const int tid  = threadIdx.x;
    const int lane = tid & 31;
    const int b    = blockIdx.x / HB_;
    const int r0   = (blockIdx.x % HB_) * ROWS;
    const int rev  = blockIdx.x & 1;      // serpentine band (halo L2 reuse)

    const float* srb = sr + (size_t)b * C_ * HW_;
    const float* hrb = hr + (size_t)b * C_ * HW_;

    // ---- Load phase: gray-diff + HORIZONTAL Sobel passes, store {h1,h2} fp16 ----
    // 18 rows x 128 chunks = 2304 tasks, 9 per thread. Warp covers 32 consecutive
    // chunks of one row (tr uniform across warp -> uniform branch, safe shfl).
    #pragma unroll
    for (int it = 0; it < (TROWS * (W_ / 4)) / TPB; ++it) {
        int idx   = tid + it * TPB;
        int trl   = idx >> 7;                        // 0..17
        int tr    = rev ? (TROWS - 1 - trl) : trl;   // serpentine
        int chunk = idx & 127;
        int gr    = r0 + tr - 1;

        float4 d = make_float4(0.f, 0.f, 0.f, 0.f);
        float dl = 0.f, dr = 0.f;
        if (gr >= 0 && gr < H_) {                    // warp-uniform
            size_t off = (size_t)gr * W_ + chunk * 4;
            float4 s0 = *(const float4*)(srb + 0 * HW_ + off);
            float4 s1 = *(const float4*)(srb + 1 * HW_ + off);
            float4 s2 = *(const float4*)(srb + 2 * HW_ + off);
            float4 h0 = *(const float4*)(hrb + 0 * HW_ + off);
            float4 h1 = *(const float4*)(hrb + 1 * HW_ + off);
            float4 h2 = *(const float4*)(hrb + 2 * HW_ + off);
            d.x = 0.2989f * (s0.x - h0.x) + 0.587f * (s1.x - h1.x) + 0.114f * (s2.x - h2.x);
            d.y = 0.2989f * (s0.y - h0.y) + 0.587f * (s1.y - h1.y) + 0.114f * (s2.y - h2.y);
            d.z = 0.2989f * (s0.z - h0.z) + 0.587f * (s1.z - h1.z) + 0.114f * (s2.z - h2.z);
            d.w = 0.2989f * (s0.w - h0.w) + 0.587f * (s1.w - h1.w) + 0.114f * (s2.w - h2.w);

            dl = __shfl_up_sync(0xFFFFFFFFu, d.w, 1);
            dr = __shfl_down_sync(0xFFFFFFFFu, d.x, 1);
            if (lane == 0)        // cross-warp (or image) left neighbor
                dl = (chunk == 0)   ? 0.f : gray1(srb, hrb, off - 1);
            if (lane == 31)       // cross-warp (or image) right neighbor
                dr = (chunk == 127) ? 0.f : gray1(srb, hrb, off + 4);
        }

        // horizontal passes: h1 = d(c-1) - d(c+1); h2 = d(c-1) + 2 d(c) + d(c+1)
        float dm[4] = { dl,  d.x, d.y, d.z };
        float dc[4] = { d.x, d.y, d.z, d.w };
        float dp[4] = { d.y, d.z, d.w, dr  };

        __half2 hv[4];
        #pragma unroll
        for (int j = 0; j < 4; ++j)
            hv[j] = __floats2half2_rn(dm[j] - dp[j],                 // h1
                                      dm[j] + 2.0f * dc[j] + dp[j]); // h2

        // one STS.128 per task (16B aligned)
        *(uint4*)&g[tr * RSTR + chunk * 4] = *(const uint4*)hv;
    }
    __syncthreads();

    // ---- Compute phase: pure vertical pass, {gx,gy} = v0 + {2,0}v1 + {1,-1}v2 ----
    const __half2 k1 = __floats2half2_rn(2.0f, 0.0f);
    const __half2 k2 = __floats2half2_rn(1.0f, -1.0f);
    float acc = 0.0f;
    #pragma unroll
    for (int it = 0; it < (ROWS * (W_ / 4)) / TPB; ++it) {   // 8 iters
        int idx = tid + it * TPB;
        int rr  = idx >> 7;            // 0..15 (tile row rr = image row r-1)
        int c4  = (idx & 127) * 4;

        uint4 u0 = *(const uint4*)&g[rr * RSTR + c4];
        uint4 u1 = *(const uint4*)&g[(rr + 1) * RSTR + c4];
        uint4 u2 = *(const uint4*)&g[(rr + 2) * RSTR + c4];
        const __half2* v0 = (const __half2*)&u0;
        const __half2* v1 = (const __half2*)&u1;
        const __half2* v2 = (const __half2*)&u2;

        __half2 s = __floats2half2_rn(0.f, 0.f);
        #pragma unroll
        for (int j = 0; j < 4; ++j) {
            __half2 w = __hfma2(k1, v1[j], v0[j]);
            w = __hfma2(k2, v2[j], w);          // w = {gx, gy}
            s = __hadd2(s, __habs2(w));
        }
        float2 sf = __half22float2(s);
        acc += sf.x + sf.y;
    }

    // Block reduce
    #pragma unroll
    for (int off = 16; off > 0; off >>= 1)
        acc += __shfl_xor_sync(0xFFFFFFFFu, acc, off);

    __shared__ float wsum[TPB / 32];
    if (lane == 0) wsum[tid >> 5] = acc;
    __syncthreads();

    // tid0: one fire-and-forget atomic per block; NO trailing barrier.
    if (tid == 0) {
        float s = 0.0f;
        #pragma unroll
        for (int w = 0; w < TPB / 32; ++w) s += wsum[w];
        atomicAdd(&g_accum, s);
        __threadfence();
        unsigned int prev = atomicAdd(&g_count, 1u);
        if (prev == NBLK - 1) {
            float tot = atomicAdd(&g_accum, 0.0f);   // coherent L2 read
            out[0] = tot / (float)(B_ * (size_t)HW_);
            g_accum = 0.0f;   // reset for next replay
            g_count = 0;
        }
    }
}

extern "C" void kernel_launch(void* const* d_in, const int* in_sizes, int n_in,
                              void* d_out, int out_size)
{
    const float* sr = (const float*)d_in[0];
    const float* hr = (const float*)d_in[1];
    float* out = (float*)d_out;

    edge_loss_kernel<<<NBLK, TPB>>>(sr, hr, out);
}

// round 16
// speedup vs baseline: 1.0775x; 1.0573x over previous
#include <cuda_runtime.h>
#include <cuda_fp16.h>

#define B_   32
#define C_   3
#define H_   512
#define W_   512
#define HW_  (H_ * W_)
#define ROWS 16
#define HB_  (H_ / ROWS)          // 32 bands per image
#define NBLK (B_ * HB_ / 2)       // 512 blocks: each CTA does 2 bands
#define TPB  256
#define TROWS (ROWS + 2)          // 18 tile rows (with halo)
#define STR  516                  // smem row stride in halves (1032 B)

// Tile layout (halves): image col c -> index c+2; left halo idx 1, right halo 514;
// indices 0 and 515 zeroed.

__device__ float g_accum = 0.0f;
__device__ unsigned int g_count = 0;

__device__ __forceinline__ void load_iter(
    __half* __restrict__ g,
    const float* __restrict__ srb, const float* __restrict__ hrb,
    int r0, int rev, int idx)
{
    int trl   = idx >> 7;                       // linear tile row 0..17
    int tr    = rev ? (TROWS - 1 - trl) : trl;  // serpentine
    int chunk = idx & 127;
    int gr    = r0 + tr - 1;

    float4 d = make_float4(0.f, 0.f, 0.f, 0.f);
    if (gr >= 0 && gr < H_) {
        size_t off = (size_t)gr * W_ + chunk * 4;
        float4 s0 = *(const float4*)(srb + 0 * HW_ + off);
        float4 s1 = *(const float4*)(srb + 1 * HW_ + off);
        float4 s2 = *(const float4*)(srb + 2 * HW_ + off);
        float4 h0 = *(const float4*)(hrb + 0 * HW_ + off);
        float4 h1 = *(const float4*)(hrb + 1 * HW_ + off);
        float4 h2 = *(const float4*)(hrb + 2 * HW_ + off);
        d.x = 0.2989f * (s0.x - h0.x) + 0.587f * (s1.x - h1.x) + 0.114f * (s2.x - h2.x);
        d.y = 0.2989f * (s0.y - h0.y) + 0.587f * (s1.y - h1.y) + 0.114f * (s2.y - h2.y);
        d.z = 0.2989f * (s0.z - h0.z) + 0.587f * (s1.z - h1.z) + 0.114f * (s2.z - h2.z);
        d.w = 0.2989f * (s0.w - h0.w) + 0.587f * (s1.w - h1.w) + 0.114f * (s2.w - h2.w);
    }
    __half2* dst = (__half2*)&g[tr * STR + 2 + chunk * 4];   // 4B-aligned
    dst[0] = __floats2half2_rn(d.x, d.y);
    dst[1] = __floats2half2_rn(d.z, d.w);
}

__device__ __forceinline__ float compute_iter(
    const __half* __restrict__ g, int idx)
{
    int rr  = idx >> 7;            // 0..15
    int c4  = (idx & 127) * 4;     // 0,4,...,508
    const __half2* p0 = (const __half2*)&g[rr * STR + c4];
    const __half2* p1 = (const __half2*)&g[(rr + 1) * STR + c4];
    const __half2* p2 = (const __half2*)&g[(rr + 2) * STR + c4];

    const __half2 two = __floats2half2_rn(2.0f, 2.0f);

    __half2 P0 = p0[0], Q0 = p0[1], R0 = p0[2], S0 = p0[3];
    __half2 P1 = p1[0], Q1 = p1[1], R1 = p1[2], S1 = p1[3];
    __half2 P2 = p2[0], Q2 = p2[1], R2 = p2[2], S2 = p2[3];

    __half2 A0r0 = __halves2half2(__high2half(P0), __low2half(Q0));
    __half2 C0r0 = __halves2half2(__high2half(Q0), __low2half(R0));
    __half2 C1r0 = __halves2half2(__high2half(R0), __low2half(S0));
    __half2 A0r1 = __halves2half2(__high2half(P1), __low2half(Q1));
    __half2 C0r1 = __halves2half2(__high2half(Q1), __low2half(R1));
    __half2 C1r1 = __halves2half2(__high2half(R1), __low2half(S1));
    __half2 A0r2 = __halves2half2(__high2half(P2), __low2half(Q2));
    __half2 C0r2 = __halves2half2(__high2half(Q2), __low2half(R2));
    __half2 C1r2 = __halves2half2(__high2half(R2), __low2half(S2));

    __half2 gx0 = __hfma2(two, __hsub2(A0r1, C0r1),
                          __hadd2(__hsub2(A0r0, C0r0), __hsub2(A0r2, C0r2)));
    __half2 gy0 = __hsub2(__hfma2(two, Q0, __hadd2(A0r0, C0r0)),
                          __hfma2(two, Q2, __hadd2(A0r2, C0r2)));
    __half2 gx1 = __hfma2(two, __hsub2(C0r1, C1r1),
                          __hadd2(__hsub2(C0r0, C1r0), __hsub2(C0r2, C1r2)));
    __half2 gy1 = __hsub2(__hfma2(two, R0, __hadd2(C0r0, C1r0)),
                          __hfma2(two, R2, __hadd2(C0r2, C1r2)));

    __half2 s2h = __hadd2(__hadd2(__habs2(gx0), __habs2(gy0)),
                          __hadd2(__habs2(gx1), __habs2(gy1)));
    float2 sf = __half22float2(s2h);
    return sf.x + sf.y;
}

__global__ __launch_bounds__(TPB, 6) void edge_loss_kernel(
    const float* __restrict__ sr, const float* __restrict__ hr,
    float* __restrict__ out)
{
    __shared__ __half gA[TROWS * STR];   // 18,576 B each -> 37,152 total, 6 CTAs/SM
    __shared__ __half gB[TROWS * STR];

    const int tid = threadIdx.x;
    const int b   = blockIdx.x >> 4;        // 16 CTA-pairs per image
    const int j   = blockIdx.x & 15;        // band pair index
    const int r0A = (2 * j) * ROWS;         // band 2j  (linear load)
    const int r0B = r0A + ROWS;             // band 2j+1 (reversed load)

    const float* srb = sr + (size_t)b * C_ * HW_;
    const float* hrb = hr + (size_t)b * C_ * HW_;

    // Zero halo columns in both buffers: indices 0,1 and 514,515 per tile row
    if (tid < 4 * TROWS) {
        int tr   = (tid >> 2);
        int k    = tid & 3;
        __half* buf = (k & 2) ? gB : gA;
        __half2* dst = (__half2*)&buf[tr * STR + ((k & 1) ? 514 : 0)];
        *dst = __floats2half2_rn(0.0f, 0.0f);
    }

    // ---- P1: load tile A (pure, fully unrolled) ----
    #pragma unroll
    for (int it = 0; it < 9; ++it)
        load_iter(gA, srb, hrb, r0A, /*rev=*/0, tid + it * TPB);
    __syncthreads();

    // ---- P2: issue tile B's full load, then compute tile A ----
    // B's LDGs are in flight / draining to STS while A-compute executes:
    // DRAM stays fed through the compute.
    #pragma unroll
    for (int it = 0; it < 9; ++it)
        load_iter(gB, srb, hrb, r0B, /*rev=*/1, tid + it * TPB);

    float acc = 0.0f;
    #pragma unroll
    for (int it = 0; it < 8; ++it)
        acc += compute_iter(gA, tid + it * TPB);
    __syncthreads();

    // ---- P3: compute tile B (tail) ----
    #pragma unroll
    for (int it = 0; it < 8; ++it)
        acc += compute_iter(gB, tid + it * TPB);

    // Block reduce
    #pragma unroll
    for (int off = 16; off > 0; off >>= 1)
        acc += __shfl_xor_sync(0xFFFFFFFFu, acc, off);

    __shared__ float wsum[TPB / 32];
    if ((tid & 31) == 0) wsum[tid >> 5] = acc;
    __syncthreads();

    // tid0: one fire-and-forget atomic per block; NO trailing barrier.
    if (tid == 0) {
        float s = 0.0f;
        #pragma unroll
        for (int w = 0; w < TPB / 32; ++w) s += wsum[w];
        atomicAdd(&g_accum, s);
        __threadfence();
        unsigned int prev = atomicAdd(&g_count, 1u);
        if (prev == NBLK - 1) {
            float tot = atomicAdd(&g_accum, 0.0f);   // coherent L2 read
            out[0] = tot / (float)(B_ * (size_t)HW_);
            g_accum = 0.0f;   // reset for next replay
            g_count = 0;
        }
    }
}

extern "C" void kernel_launch(void* const* d_in, const int* in_sizes, int n_in,
                              void* d_out, int out_size)
{
    const float* sr = (const float*)d_in[0];
    const float* hr = (const float*)d_in[1];
    float* out = (float*)d_out;

    edge_loss_kernel<<<NBLK, TPB>>>(sr, hr, out);
}

// round 17
// speedup vs baseline: 1.3358x; 1.2397x over previous
#include <cuda_runtime.h>
#include <cuda_fp16.h>

#define B_   32
#define C_   3
#define H_   512
#define W_   512
#define HW_  (H_ * W_)
#define ROWS 16
#define HB_  (H_ / ROWS)          // 32 row-bands per image
#define NBLK (B_ * HB_)           // 1024 blocks
#define TPB  256
#define TROWS (ROWS + 2)          // 18 tile rows (with halo)
#define STR  516                  // smem row stride in halves (1032 B)

// Tile layout (halves): image col c -> index c+2; left halo idx 1, right halo 514;
// indices 0 and 515 zeroed.

__device__ float g_accum = 0.0f;
__device__ unsigned int g_count = 0;

__device__ __forceinline__ void load_iter(
    __half* __restrict__ g,
    const float* __restrict__ srb, const float* __restrict__ hrb,
    int r0, int rev, int idx)
{
    int trl   = idx >> 7;                       // linear tile row 0..17
    int tr    = rev ? (TROWS - 1 - trl) : trl;  // serpentine
    int chunk = idx & 127;
    int gr    = r0 + tr - 1;

    float4 d = make_float4(0.f, 0.f, 0.f, 0.f);
    if (gr >= 0 && gr < H_) {
        size_t off = (size_t)gr * W_ + chunk * 4;
        float4 s0 = *(const float4*)(srb + 0 * HW_ + off);
        float4 s1 = *(const float4*)(srb + 1 * HW_ + off);
        float4 s2 = *(const float4*)(srb + 2 * HW_ + off);
        float4 h0 = *(const float4*)(hrb + 0 * HW_ + off);
        float4 h1 = *(const float4*)(hrb + 1 * HW_ + off);
        float4 h2 = *(const float4*)(hrb + 2 * HW_ + off);
        d.x = 0.2989f * (s0.x - h0.x) + 0.587f * (s1.x - h1.x) + 0.114f * (s2.x - h2.x);
        d.y = 0.2989f * (s0.y - h0.y) + 0.587f * (s1.y - h1.y) + 0.114f * (s2.y - h2.y);
        d.z = 0.2989f * (s0.z - h0.z) + 0.587f * (s1.z - h1.z) + 0.114f * (s2.z - h2.z);
        d.w = 0.2989f * (s0.w - h0.w) + 0.587f * (s1.w - h1.w) + 0.114f * (s2.w - h2.w);
    }
    __half2* dst = (__half2*)&g[tr * STR + 2 + chunk * 4];   // 4B-aligned
    dst[0] = __floats2half2_rn(d.x, d.y);
    dst[1] = __floats2half2_rn(d.z, d.w);
}

__device__ __forceinline__ float compute_iter(
    const __half* __restrict__ g, int rev, int idx)
{
    int rrl = idx >> 7;                     // linear pixel row 0..15
    int rr  = rev ? (ROWS - 1 - rrl) : rrl; // serpentine (match load order)
    int c4  = (idx & 127) * 4;              // 0,4,...,508
    const __half2* p0 = (const __half2*)&g[rr * STR + c4];
    const __half2* p1 = (const __half2*)&g[(rr + 1) * STR + c4];
    const __half2* p2 = (const __half2*)&g[(rr + 2) * STR + c4];

    const __half2 two = __floats2half2_rn(2.0f, 2.0f);

    __half2 P0 = p0[0], Q0 = p0[1], R0 = p0[2], S0 = p0[3];
    __half2 P1 = p1[0], Q1 = p1[1], R1 = p1[2], S1 = p1[3];
    __half2 P2 = p2[0], Q2 = p2[1], R2 = p2[2], S2 = p2[3];

    __half2 A0r0 = __halves2half2(__high2half(P0), __low2half(Q0));
    __half2 C0r0 = __halves2half2(__high2half(Q0), __low2half(R0));
    __half2 C1r0 = __halves2half2(__high2half(R0), __low2half(S0));
    __half2 A0r1 = __halves2half2(__high2half(P1), __low2half(Q1));
    __half2 C0r1 = __halves2half2(__high2half(Q1), __low2half(R1));
    __half2 C1r1 = __halves2half2(__high2half(R1), __low2half(S1));
    __half2 A0r2 = __halves2half2(__high2half(P2), __low2half(Q2));
    __half2 C0r2 = __halves2half2(__high2half(Q2), __low2half(R2));
    __half2 C1r2 = __halves2half2(__high2half(R2), __low2half(S2));

    __half2 gx0 = __hfma2(two, __hsub2(A0r1, C0r1),
                          __hadd2(__hsub2(A0r0, C0r0), __hsub2(A0r2, C0r2)));
    __half2 gy0 = __hsub2(__hfma2(two, Q0, __hadd2(A0r0, C0r0)),
                          __hfma2(two, Q2, __hadd2(A0r2, C0r2)));
    __half2 gx1 = __hfma2(two, __hsub2(C0r1, C1r1),
                          __hadd2(__hsub2(C0r0, C1r0), __hsub2(C0r2, C1r2)));
    __half2 gy1 = __hsub2(__hfma2(two, R0, __hadd2(C0r0, C1r0)),
                          __hfma2(two, R2, __hadd2(C0r2, C1r2)));

    __half2 s2h = __hadd2(__hadd2(__habs2(gx0), __habs2(gy0)),
                          __hadd2(__habs2(gx1), __habs2(gy1)));
    float2 sf = __half22float2(s2h);
    return sf.x + sf.y;
}

__global__ __launch_bounds__(TPB, 8) void edge_loss_kernel(
    const float* __restrict__ sr, const float* __restrict__ hr,
    float* __restrict__ out)
{
    __shared__ __half g[TROWS * STR];   // 18,576 B -> 8 CTAs/SM (single wave)

    const int tid = threadIdx.x;
    const int b   = blockIdx.x / HB_;
    const int r0  = (blockIdx.x % HB_) * ROWS;
    const int rev = blockIdx.x & 1;     // serpentine band (halo L2 reuse)

    const float* srb = sr + (size_t)b * C_ * HW_;
    const float* hrb = hr + (size_t)b * C_ * HW_;

    // Zero halo columns: indices 0,1 (left) and 514,515 (right) per tile row
    if (tid < 2 * TROWS) {
        int tr   = tid >> 1;
        int side = tid & 1;
        __half2* dst = (__half2*)&g[tr * STR + (side ? 514 : 0)];
        *dst = __floats2half2_rn(0.0f, 0.0f);
    }

    // P1: load linear tile rows 0..9 (5 iters, pure)
    #pragma unroll
    for (int it = 0; it < 5; ++it)
        load_iter(g, srb, hrb, r0, rev, tid + it * TPB);
    __syncthreads();

    // P2: GROUPED — issue all remaining loads (rows 10..17, 4 iters) first,
    // then compute pixel rows 0..7 (4 iters). The batched LDGs drain into STS
    // while the grouped compute executes -> DRAM stays fed into the compute.
    #pragma unroll
    for (int it = 0; it < 4; ++it)
        load_iter(g, srb, hrb, r0, rev, tid + (5 + it) * TPB);

    float acc = 0.0f;
    #pragma unroll
    for (int it = 0; it < 4; ++it)
        acc += compute_iter(g, rev, tid + it * TPB);
    __syncthreads();

    // P3: compute pixel rows 8..15 (4 iters)
    #pragma unroll
    for (int it = 0; it < 4; ++it)
        acc += compute_iter(g, rev, tid + (4 + it) * TPB);

    // Block reduce
    #pragma unroll
    for (int off = 16; off > 0; off >>= 1)
        acc += __shfl_xor_sync(0xFFFFFFFFu, acc, off);

    __shared__ float wsum[TPB / 32];
    if ((tid & 31) == 0) wsum[tid >> 5] = acc;
    __syncthreads();

    // tid0: one fire-and-forget atomic per block; NO trailing barrier.
    if (tid == 0) {
        float s = 0.0f;
        #pragma unroll
        for (int w = 0; w < TPB / 32; ++w) s += wsum[w];
        atomicAdd(&g_accum, s);
        __threadfence();
        unsigned int prev = atomicAdd(&g_count, 1u);
        if (prev == NBLK - 1) {
            float tot = atomicAdd(&g_accum, 0.0f);   // coherent L2 read
            out[0] = tot / (float)(B_ * (size_t)HW_);
            g_accum = 0.0f;   // reset for next replay
            g_count = 0;
        }
    }
}

extern "C" void kernel_launch(void* const* d_in, const int* in_sizes, int n_in,
                              void* d_out, int out_size)
{
    const float* sr = (const float*)d_in[0];
    const float* hr = (const float*)d_in[1];
    float* out = (float*)d_out;

    edge_loss_kernel<<<NBLK, TPB>>>(sr, hr, out);
}